// round 11
// baseline (speedup 1.0000x reference)
#include <cuda_runtime.h>
#include <stdint.h>

// MaskPyramids, FLAT single-pass: blocks cover contiguous 4096-float slices
// of the flat [512*53294] output, so every warp's 512B store run is 128B-line
// aligned and every store is STG.128 -- identical store pattern to a pure
// zero-fill (the measured 109MB floor). Decode per 16B chunk: one compare for
// instance (block spans <=2 instances; division done once per thread), a
// level compare-chain with magic-div row/col, window predicate, gather/zeros.
//
// Rounding replicates XLA's div->reciprocal-mul rewrite (verified exact R3):
//   rint( fl( fl(p * fl(1/200)) * H ) ), all f32 RN-even.

#define N_INST   512
#define G        28
#define CTRK     13
#define PER_INST 53294                     // 40000+10000+2500+625+169
#define TOTAL    (N_INST * PER_INST)       // 27,286,528 floats
#define TOTAL_F4 (TOTAL / 4)               // 6,821,632
#define F4_PER_BLOCK 1024
#define NBLOCKS  ((TOTAL_F4 + F4_PER_BLOCK - 1) / F4_PER_BLOCK)  // 6662

__global__ void __launch_bounds__(256)
flat_kernel(const int* __restrict__ pos,
            const float* __restrict__ mask,
            float* __restrict__ out) {
    const int bid = blockIdx.x;
    const unsigned base_off = (unsigned)bid * (F4_PER_BLOCK * 4);

    // Block spans at most 2 instances: find them once.
    const unsigned instA = base_off / (unsigned)PER_INST;   // compiler magic div
    const unsigned instB = (instA + 1 < N_INST) ? instA + 1 : instA;
    const unsigned baseA = instA * (unsigned)PER_INST;
    const unsigned lim   = baseA + PER_INST;                // start of instB

    const float recip = 0.005f;  // fl(1/200) bit-exactly
    const float ppA0 = __fmul_rn((float)__ldg(&pos[2 * instA + 0]), recip);
    const float ppA1 = __fmul_rn((float)__ldg(&pos[2 * instA + 1]), recip);
    const float ppB0 = __fmul_rn((float)__ldg(&pos[2 * instB + 0]), recip);
    const float ppB1 = __fmul_rn((float)__ldg(&pos[2 * instB + 1]), recip);

    #pragma unroll
    for (int k = 0; k < 4; k++) {
        const unsigned f4 = (unsigned)bid * F4_PER_BLOCK + k * 256 + threadIdx.x;
        if (f4 >= TOTAL_F4) break;
        const unsigned off = f4 * 4;

        const bool inB = (off >= lim);
        const unsigned loffI = off - (inB ? lim : baseA);   // offset within row
        const float pp0 = inB ? ppB0 : ppA0;
        const float pp1 = inB ? ppB1 : ppA1;

        // level select (magic constants exact for loff < 2^32/H; verified R4)
        int lbase, H; unsigned M; float Hf;
        if (loffI < 40000u)      { lbase = 0;     H = 200; M = 21474837u;  Hf = 200.f; }
        else if (loffI < 50000u) { lbase = 40000; H = 100; M = 42949673u;  Hf = 100.f; }
        else if (loffI < 52500u) { lbase = 50000; H = 50;  M = 85899346u;  Hf = 50.f;  }
        else if (loffI < 53125u) { lbase = 52500; H = 25;  M = 171798692u; Hf = 25.f;  }
        else                     { lbase = 53125; H = 13;  M = 330382100u; Hf = 13.f;  }

        const unsigned loff = loffI - (unsigned)lbase;
        const int row = (int)__umulhi(loff, M);             // exact loff/H
        const int col = (int)loff - row * H;

        // XLA-faithful center
        const int lh = (int)rintf(__fmul_rn(pp0, Hf));
        const int lw = (int)rintf(__fmul_rn(pp1, Hf));
        const int si = row + (CTRK - lh);
        const int sj = col - (lw - CTRK);

        float4 v = make_float4(0.f, 0.f, 0.f, 0.f);
        // Chunk may straddle a row (levels with H%4!=0 or level boundaries are
        // handled by the straddle path too). Fast path: fully inside one row.
        const bool onerow = (col + 3 < H) && (loffI + 3 < (unsigned)(lbase + H * (row + 1)) + 0u);
        if (onerow) {
            if ((unsigned)si < (unsigned)G && sj > -4 && sj < G) {
                const float* mrow = mask + si * G;
                if ((unsigned)(sj + 0) < (unsigned)G) v.x = __ldg(&mrow[sj + 0]);
                if ((unsigned)(sj + 1) < (unsigned)G) v.y = __ldg(&mrow[sj + 1]);
                if ((unsigned)(sj + 2) < (unsigned)G) v.z = __ldg(&mrow[sj + 2]);
                if ((unsigned)(sj + 3) < (unsigned)G) v.w = __ldg(&mrow[sj + 3]);
            }
        } else {
            // generic per-element path (row straddle / level or inst boundary)
            float ve[4];
            #pragma unroll
            for (int e = 0; e < 4; e++) {
                const unsigned o = off + e;
                const bool eB = (o >= lim);
                const unsigned lo = o - (eB ? lim : baseA);
                const float q0 = eB ? ppB0 : ppA0;
                const float q1 = eB ? ppB1 : ppA1;
                int lb, h; unsigned m; float hf;
                if (lo < 40000u)      { lb = 0;     h = 200; m = 21474837u;  hf = 200.f; }
                else if (lo < 50000u) { lb = 40000; h = 100; m = 42949673u;  hf = 100.f; }
                else if (lo < 52500u) { lb = 50000; h = 50;  m = 85899346u;  hf = 50.f;  }
                else if (lo < 53125u) { lb = 52500; h = 25;  m = 171798692u; hf = 25.f;  }
                else                  { lb = 53125; h = 13;  m = 330382100u; hf = 13.f;  }
                const unsigned l2 = lo - (unsigned)lb;
                const int r = (int)__umulhi(l2, m);
                const int c = (int)l2 - r * h;
                const int eh = (int)rintf(__fmul_rn(q0, hf));
                const int ew = (int)rintf(__fmul_rn(q1, hf));
                const int s1 = r + (CTRK - eh);
                const int s2 = c - (ew - CTRK);
                ve[e] = ((unsigned)s1 < (unsigned)G && (unsigned)s2 < (unsigned)G)
                            ? __ldg(&mask[s1 * G + s2]) : 0.0f;
            }
            v = make_float4(ve[0], ve[1], ve[2], ve[3]);
        }

        *reinterpret_cast<float4*>(out + off) = v;   // STG.128, line-aligned warps
    }
}

extern "C" void kernel_launch(void* const* d_in, const int* in_sizes, int n_in,
                              void* d_out, int out_size) {
    const int*   pos  = (const int*)d_in[0];      // int32 [512, 2]
    const float* mask = (const float*)d_in[1];    // float32 [28, 28]
    float*       out  = (float*)d_out;            // float32 [512, 53294]

    flat_kernel<<<NBLOCKS, 256>>>(pos, mask, out);
}

// round 12
// speedup vs baseline: 1.4124x; 1.4124x over previous
#include <cuda_runtime.h>
#include <stdint.h>

// MaskPyramids single-pass, single-launch, per-region 128B-line-aligned
// stores. Blocks are (instance, level)-specialized (slim decode, R10 shape);
// within each level region the bulk coverage starts at the first 128B line
// boundary (head h = (-start) mod 32 elems, tail <= 3 elems handled scalar by
// spare threads of chunk 0), so every warp's 512B STG.128 run covers exactly
// 4 cache lines -- the zero-fill store pattern.
//
// grid = (14, 512): bx 0-9 -> level 200x200, bx 10-12 -> level 100x100,
// bx 13 -> levels 50/25/13 (scalar tail levels).
//
// Rounding replicates XLA's div->reciprocal-mul rewrite (verified exact R3):
//   rint( fl( fl(p * fl(1/200)) * H ) ), all f32 RN-even.

#define N_INST   512
#define G        28
#define CTRK     13
#define PER_INST 53294   // 40000 + 10000 + 2500 + 625 + 169

__device__ __forceinline__ float mval(const float* __restrict__ mask,
                                      int si, int sj) {
    return ((unsigned)si < (unsigned)G && (unsigned)sj < (unsigned)G)
               ? __ldg(&mask[si * G + sj]) : 0.0f;
}

template<int H, int BASE>
__device__ __forceinline__ void do_level(int chunk, int c0, int b0, int h,
                                         const float* __restrict__ mask,
                                         float* __restrict__ outlevel) {
    constexpr int NELEM = H * H;
    const int NB = (NELEM - h) >> 2;        // aligned-body f4 count
    const int tid = threadIdx.x;

    #pragma unroll
    for (int k = 0; k < 4; k++) {
        const int f4 = chunk * 1024 + k * 256 + tid;
        if (f4 < NB) {
            const int off = h + f4 * 4;
            const int row = off / H;            // compile-time magic div
            const int col = off - row * H;
            const int si  = row + c0;
            float4 v = make_float4(0.f, 0.f, 0.f, 0.f);
            if (col <= H - 4) {                 // no row straddle (common)
                const int sj = col - b0;
                if ((unsigned)si < (unsigned)G && sj > -4 && sj < G) {
                    const float* mrow = mask + si * G;
                    if ((unsigned)(sj + 0) < (unsigned)G) v.x = __ldg(&mrow[sj + 0]);
                    if ((unsigned)(sj + 1) < (unsigned)G) v.y = __ldg(&mrow[sj + 1]);
                    if ((unsigned)(sj + 2) < (unsigned)G) v.z = __ldg(&mrow[sj + 2]);
                    if ((unsigned)(sj + 3) < (unsigned)G) v.w = __ldg(&mrow[sj + 3]);
                }
            } else {                            // straddle (h%4!=0 only, rare)
                float ve[4];
                #pragma unroll
                for (int e = 0; e < 4; e++) {
                    int c = col + e, r = si;
                    if (c >= H) { c -= H; r += 1; }
                    ve[e] = mval(mask, r, c - b0);
                }
                v = make_float4(ve[0], ve[1], ve[2], ve[3]);
            }
            *reinterpret_cast<float4*>(outlevel + off) = v;  // aligned STG.128
        }
    }

    if (chunk == 0) {
        // head: elements [0, h), all in row 0
        if (tid < h)
            outlevel[tid] = mval(mask, c0, tid - b0);
        // tail: t = (NELEM - h) & 3 elements at the very end, row H-1
        const int t = (NELEM - h) & 3;
        const int j = tid - 64;
        if (j >= 0 && j < t)
            outlevel[NELEM - t + j] = mval(mask, H - 1 + c0, H - t + j - b0);
    }
}

template<int H, int BASE, int N>
__device__ __forceinline__ void do_tail_level(float pp0, float pp1,
                                              const float* __restrict__ mask,
                                              float* __restrict__ outrow) {
    const int lh = (int)rintf(__fmul_rn(pp0, (float)H));
    const int lw = (int)rintf(__fmul_rn(pp1, (float)H));
    const int c0 = CTRK - lh;
    const int b0 = lw - CTRK;
    for (int idx = threadIdx.x; idx < N; idx += 256) {
        const int row = idx / H;                // compile-time magic div
        const int col = idx - row * H;
        outrow[BASE + idx] = mval(mask, row + c0, col - b0);
    }
}

__global__ void __launch_bounds__(256)
fused_kernel(const int* __restrict__ pos,
             const float* __restrict__ mask,
             float* __restrict__ out) {
    const int inst = blockIdx.y;
    const int bx   = blockIdx.x;

    const float recip = 0.005f;  // fl(1/200) bit-exactly
    const float pp0 = __fmul_rn((float)__ldg(&pos[2 * inst + 0]), recip);
    const float pp1 = __fmul_rn((float)__ldg(&pos[2 * inst + 1]), recip);

    float* outrow = out + inst * PER_INST;
    // head length to first 128B line: start of levels 0 and 1 are both
    // inst*53294 (+40000, which is 0 mod 32) -> same h for both.
    const int h = (32 - ((inst * PER_INST) & 31)) & 31;

    if (bx < 10) {
        const int c0 = CTRK - (int)rintf(__fmul_rn(pp0, 200.f));
        const int b0 = (int)rintf(__fmul_rn(pp1, 200.f)) - CTRK;
        do_level<200, 0>(bx, c0, b0, h, mask, outrow);
    } else if (bx < 13) {
        const int c0 = CTRK - (int)rintf(__fmul_rn(pp0, 100.f));
        const int b0 = (int)rintf(__fmul_rn(pp1, 100.f)) - CTRK;
        do_level<100, 40000>(bx - 10, c0, b0, h, mask, outrow + 40000);
    } else {
        do_tail_level<50, 50000, 2500>(pp0, pp1, mask, outrow);
        do_tail_level<25, 52500, 625>(pp0, pp1, mask, outrow);
        do_tail_level<13, 53125, 169>(pp0, pp1, mask, outrow);
    }
}

extern "C" void kernel_launch(void* const* d_in, const int* in_sizes, int n_in,
                              void* d_out, int out_size) {
    const int*   pos  = (const int*)d_in[0];      // int32 [512, 2]
    const float* mask = (const float*)d_in[1];    // float32 [28, 28]
    float*       out  = (float*)d_out;            // float32 [512, 53294]

    fused_kernel<<<dim3(14, N_INST), 256>>>(pos, mask, out);
}